// round 3
// baseline (speedup 1.0000x reference)
#include <cuda_runtime.h>
#include <math.h>

#define NN 200000
#define EE 6400000
#define MM 10000
#define SCAN_CHUNK 2048
#define SCAN_NB 98   // ceil(NN / SCAN_CHUNK)

// ---------------- device scratch (no allocations allowed) ----------------
__device__ __align__(16) int   g_cnt[NN];
__device__ __align__(16) int   g_off[NN];
__device__ __align__(16) int   g_cursor[NN];
__device__ __align__(16) int   g_bsum[128];
__device__ __align__(16) int   g_csr[EE];
__device__ __align__(16) float g_h1[(size_t)NN * 16];   // dinv[i] * (x @ W1)[i]
__device__ __align__(16) float g_hw2[(size_t)NN * 2];   // dinv[i] * (relu(layer1) @ W2)[i]
__device__ __align__(16) float g_bp[MM * 5];
__device__ __align__(16) unsigned g_minmax[2];          // [0]=min enc, [1]=max enc

// ordered-uint encoding so unsigned atomicMin/Max give float min/max
__device__ __forceinline__ unsigned fenc(float f) {
    unsigned u = __float_as_uint(f);
    return (u & 0x80000000u) ? ~u : (u | 0x80000000u);
}
__device__ __forceinline__ float fdec(unsigned u) {
    return (u & 0x80000000u) ? __uint_as_float(u & 0x7fffffffu)
                             : __uint_as_float(~u);
}

// ---------------- kernels ----------------

__global__ void k_zero() {
    int i = blockIdx.x * blockDim.x + threadIdx.x;
    if (i < NN) g_cnt[i] = 0;
    if (i == 0) { g_minmax[0] = 0xFFFFFFFFu; g_minmax[1] = 0u; }
}

__global__ void k_hist(const int* __restrict__ dst) {
    int e = blockIdx.x * blockDim.x + threadIdx.x;
    if (e < EE) atomicAdd(&g_cnt[dst[e]], 1);
}

__global__ void k_scan_a() {
    __shared__ int sh[512];
    int b = blockIdx.x, t = threadIdx.x;
    int base = b * SCAN_CHUNK + t * 4;
    int s = 0;
#pragma unroll
    for (int i = 0; i < 4; i++) { int idx = base + i; if (idx < NN) s += g_cnt[idx]; }
    sh[t] = s; __syncthreads();
    for (int o = 256; o > 0; o >>= 1) {
        if (t < o) sh[t] += sh[t + o];
        __syncthreads();
    }
    if (t == 0) g_bsum[b] = sh[0];
}

__global__ void k_scan_b() {
    __shared__ int sh[128];
    int t = threadIdx.x;
    int v = (t < SCAN_NB) ? g_bsum[t] : 0;
    sh[t] = v; __syncthreads();
    for (int o = 1; o < 128; o <<= 1) {
        int u = (t >= o) ? sh[t - o] : 0;
        __syncthreads();
        sh[t] += u;
        __syncthreads();
    }
    if (t < SCAN_NB) g_bsum[t] = sh[t] - v;   // exclusive
}

__global__ void k_scan_c() {
    __shared__ int sh[512];
    int b = blockIdx.x, t = threadIdx.x;
    int base = b * SCAN_CHUNK + t * 4;
    int v[4]; int s = 0;
#pragma unroll
    for (int i = 0; i < 4; i++) {
        int idx = base + i;
        v[i] = (idx < NN) ? g_cnt[idx] : 0;
        s += v[i];
    }
    sh[t] = s; __syncthreads();
    for (int o = 1; o < 512; o <<= 1) {
        int u = (t >= o) ? sh[t - o] : 0;
        __syncthreads();
        sh[t] += u;
        __syncthreads();
    }
    int ex = sh[t] - s + g_bsum[b];
#pragma unroll
    for (int i = 0; i < 4; i++) {
        int idx = base + i;
        if (idx < NN) { g_off[idx] = ex; g_cursor[idx] = ex; ex += v[i]; }
    }
}

__global__ void k_scatter(const int* __restrict__ src, const int* __restrict__ dst) {
    int e = blockIdx.x * blockDim.x + threadIdx.x;
    if (e < EE) {
        int d = dst[e];
        int idx = atomicAdd(&g_cursor[d], 1);
        g_csr[idx] = src[e];
    }
}

// h1'[row] = dinv[row] * (x[row,:] @ W1)     x:[NN,100] W1:[100,16]
__global__ void k_gemm(const float* __restrict__ x, const float* __restrict__ W1) {
    __shared__ __align__(16) float sx[64 * 100];
    __shared__ __align__(16) float sw[100 * 16];
    int b = blockIdx.x, t = threadIdx.x;
    size_t row0 = (size_t)b * 64;

    const float4* xg = (const float4*)(x + row0 * 100);   // 400B row stride -> 16B aligned
    float4* sx4 = (float4*)sx;
#pragma unroll
    for (int i = 0; i < 7; i++) { int idx = t + i * 256; if (idx < 1600) sx4[idx] = xg[idx]; }
    const float4* wg = (const float4*)W1;
    float4* sw4 = (float4*)sw;
#pragma unroll
    for (int i = 0; i < 2; i++) { int idx = t + i * 256; if (idx < 400) sw4[idx] = wg[idx]; }
    __syncthreads();

    int j = t & 15, rg = t >> 4;   // j: out col, rg: row group (0..15), rows rg+16m
    float a0 = 0.f, a1 = 0.f, a2 = 0.f, a3 = 0.f;
#pragma unroll 4
    for (int k = 0; k < 100; k++) {
        float w = sw[k * 16 + j];
        a0 += sx[(rg +  0) * 100 + k] * w;
        a1 += sx[(rg + 16) * 100 + k] * w;
        a2 += sx[(rg + 32) * 100 + k] * w;
        a3 += sx[(rg + 48) * 100 + k] * w;
    }
    int r0 = (int)row0;
    float d0 = rsqrtf((float)g_cnt[r0 + rg +  0] + 1.0f);
    float d1 = rsqrtf((float)g_cnt[r0 + rg + 16] + 1.0f);
    float d2 = rsqrtf((float)g_cnt[r0 + rg + 32] + 1.0f);
    float d3 = rsqrtf((float)g_cnt[r0 + rg + 48] + 1.0f);
    g_h1[(size_t)(r0 + rg +  0) * 16 + j] = a0 * d0;
    g_h1[(size_t)(r0 + rg + 16) * 16 + j] = a1 * d1;
    g_h1[(size_t)(r0 + rg + 32) * 16 + j] = a2 * d2;
    g_h1[(size_t)(r0 + rg + 48) * 16 + j] = a3 * d3;
}

// Pull aggregation layer 1, fused with bias+relu+(@W2)+dinv scaling.
// One warp per node; 4 lanes per edge (each lane = one float4 column group).
__global__ void k_pass1(const float* __restrict__ b1, const float* __restrict__ W2) {
    int warp = (blockIdx.x * blockDim.x + threadIdx.x) >> 5;
    int lane = threadIdx.x & 31;
    if (warp >= NN) return;
    int node = warp;
    int ndeg = g_cnt[node];
    int off  = g_off[node];
    int eg = lane >> 2, c = lane & 3;
    const unsigned FULL = 0xffffffffu;

    float4 acc = make_float4(0.f, 0.f, 0.f, 0.f);
    for (int base = 0; base < ndeg; base += 8) {
        int sv = 0;
        int li = base + lane;
        if (lane < 8 && li < ndeg) sv = g_csr[off + li];
        int s = __shfl_sync(FULL, sv, eg);
        if (base + eg < ndeg) {
            float4 v = *reinterpret_cast<const float4*>(&g_h1[(size_t)s * 16 + (c << 2)]);
            acc.x += v.x; acc.y += v.y; acc.z += v.z; acc.w += v.w;
        }
    }
#pragma unroll
    for (int o = 4; o < 32; o <<= 1) {
        acc.x += __shfl_xor_sync(FULL, acc.x, o);
        acc.y += __shfl_xor_sync(FULL, acc.y, o);
        acc.z += __shfl_xor_sync(FULL, acc.z, o);
        acc.w += __shfl_xor_sync(FULL, acc.w, o);
    }
    // all lanes now hold total for their column-group c
    float4 self = *reinterpret_cast<const float4*>(&g_h1[(size_t)node * 16 + (c << 2)]);
    float dv = rsqrtf((float)ndeg + 1.0f);
    float4 r;
    r.x = fmaxf(dv * (acc.x + self.x) + __ldg(&b1[c * 4 + 0]), 0.f);
    r.y = fmaxf(dv * (acc.y + self.y) + __ldg(&b1[c * 4 + 1]), 0.f);
    r.z = fmaxf(dv * (acc.z + self.z) + __ldg(&b1[c * 4 + 2]), 0.f);
    r.w = fmaxf(dv * (acc.w + self.w) + __ldg(&b1[c * 4 + 3]), 0.f);
    // partial dot with W2 [16,2]
    float p0 = r.x * __ldg(&W2[(c * 4 + 0) * 2 + 0]) + r.y * __ldg(&W2[(c * 4 + 1) * 2 + 0])
             + r.z * __ldg(&W2[(c * 4 + 2) * 2 + 0]) + r.w * __ldg(&W2[(c * 4 + 3) * 2 + 0]);
    float p1 = r.x * __ldg(&W2[(c * 4 + 0) * 2 + 1]) + r.y * __ldg(&W2[(c * 4 + 1) * 2 + 1])
             + r.z * __ldg(&W2[(c * 4 + 2) * 2 + 1]) + r.w * __ldg(&W2[(c * 4 + 3) * 2 + 1]);
    p0 += __shfl_xor_sync(FULL, p0, 1); p0 += __shfl_xor_sync(FULL, p0, 2);
    p1 += __shfl_xor_sync(FULL, p1, 1); p1 += __shfl_xor_sync(FULL, p1, 2);
    if (lane == 0) {
        g_hw2[(size_t)node * 2 + 0] = dv * p0;
        g_hw2[(size_t)node * 2 + 1] = dv * p1;
    }
}

// Pull aggregation layer 2 ONLY for nodes d = 20*m, fused with bias,
// log_softmax, BP assembly, and global min/max.
__global__ void k_pass2(const float* __restrict__ tE, const float* __restrict__ cE,
                        const float* __restrict__ pE, const float* __restrict__ b2) {
    int warp = (blockIdx.x * blockDim.x + threadIdx.x) >> 5;
    int lane = threadIdx.x & 31;
    if (warp >= MM) return;
    int m = warp;
    int d = m * 20;
    int ndeg = g_cnt[d];
    int off  = g_off[d];
    float a0 = 0.f, a1 = 0.f;
    for (int i = lane; i < ndeg; i += 32) {
        int s = g_csr[off + i];
        float2 v = *reinterpret_cast<const float2*>(&g_hw2[(size_t)s * 2]);
        a0 += v.x; a1 += v.y;
    }
    const unsigned FULL = 0xffffffffu;
#pragma unroll
    for (int o = 16; o > 0; o >>= 1) {
        a0 += __shfl_xor_sync(FULL, a0, o);
        a1 += __shfl_xor_sync(FULL, a1, o);
    }
    if (lane == 0) {
        float2 sv = *reinterpret_cast<const float2*>(&g_hw2[(size_t)d * 2]);
        a0 += sv.x; a1 += sv.y;
        float dv = rsqrtf((float)ndeg + 1.0f);
        float z0 = dv * a0 + __ldg(&b2[0]);
        float z1 = dv * a1 + __ldg(&b2[1]);
        float mx = fmaxf(z0, z1);
        float lse = mx + logf(expf(z0 - mx) + expf(z1 - mx));
        float ls0 = z0 - lse, ls1 = z1 - lse;
        float v0 = __ldg(&tE[m]), v1 = __ldg(&cE[m]), v2 = __ldg(&pE[m]);
        g_bp[m * 5 + 0] = v0;
        g_bp[m * 5 + 1] = v1;
        g_bp[m * 5 + 2] = v2;
        g_bp[m * 5 + 3] = ls0;
        g_bp[m * 5 + 4] = ls1;
        float mn  = fminf(fminf(v0, v1), fminf(v2, fminf(ls0, ls1)));
        float mxv = fmaxf(fmaxf(v0, v1), fmaxf(v2, fmaxf(ls0, ls1)));
        atomicMin(&g_minmax[0], fenc(mn));
        atomicMax(&g_minmax[1], fenc(mxv));
    }
}

// min-max normalize + 5->80->10->1 MLP + sigmoid
__global__ void k_mlp(const float* __restrict__ W1, const float* __restrict__ b1,
                      const float* __restrict__ W2, const float* __restrict__ b2,
                      const float* __restrict__ W3, const float* __restrict__ b3,
                      float* __restrict__ out) {
    __shared__ float sW1[400], sb1[80], sW2[800], sb2[10], sW3[10];
    __shared__ float sb3v, smn, ssc;
    int t = threadIdx.x;
    for (int i = t; i < 400; i += 256) sW1[i] = W1[i];
    for (int i = t; i < 80;  i += 256) sb1[i] = b1[i];
    for (int i = t; i < 800; i += 256) sW2[i] = W2[i];
    if (t < 10) { sb2[t] = b2[t]; sW3[t] = W3[t]; }
    if (t == 0) {
        sb3v = b3[0];
        smn = fdec(g_minmax[0]);
        float mxv = fdec(g_minmax[1]);
        ssc = 1.0f / (mxv - smn);
    }
    __syncthreads();
    int m = blockIdx.x * blockDim.x + t;
    if (m >= MM) return;
    float in[5];
#pragma unroll
    for (int i = 0; i < 5; i++) in[i] = (g_bp[m * 5 + i] - smn) * ssc;
    float h2[10];
#pragma unroll
    for (int q = 0; q < 10; q++) h2[q] = sb2[q];
    for (int o = 0; o < 80; o++) {
        float a = sb1[o];
#pragma unroll
        for (int i = 0; i < 5; i++) a += in[i] * sW1[i * 80 + o];
        a = fmaxf(a, 0.f);
#pragma unroll
        for (int q = 0; q < 10; q++) h2[q] += a * sW2[o * 10 + q];
    }
    float v = sb3v;
#pragma unroll
    for (int q = 0; q < 10; q++) v += fmaxf(h2[q], 0.f) * sW3[q];
    out[m] = 1.0f / (1.0f + expf(-v));
}

// ---------------- launch ----------------
extern "C" void kernel_launch(void* const* d_in, const int* in_sizes, int n_in,
                              void* d_out, int out_size) {
    const int*   ei   = (const int*)d_in[0];    // batch1_edge_index [2,E]
    const float* x    = (const float*)d_in[1];  // batch1_x [N,100]
    const float* tE   = (const float*)d_in[4];
    const float* cE   = (const float*)d_in[5];
    const float* pE   = (const float*)d_in[6];
    const float* ghW1 = (const float*)d_in[8];
    const float* ghb1 = (const float*)d_in[9];
    const float* ghW2 = (const float*)d_in[10];
    const float* ghb2 = (const float*)d_in[11];
    const float* mW1  = (const float*)d_in[16];
    const float* mb1  = (const float*)d_in[17];
    const float* mW2  = (const float*)d_in[18];
    const float* mb2  = (const float*)d_in[19];
    const float* mW3  = (const float*)d_in[20];
    const float* mb3  = (const float*)d_in[21];
    // batch2_*, edit_input, gt_* are dead in the reference output — skipped.

    const int* src = ei;
    const int* dst = ei + EE;
    float* out = (float*)d_out;

    k_zero   <<<(NN + 255) / 256, 256>>>();
    k_hist   <<<(EE + 255) / 256, 256>>>(dst);
    k_scan_a <<<SCAN_NB, 512>>>();
    k_scan_b <<<1, 128>>>();
    k_scan_c <<<SCAN_NB, 512>>>();
    k_scatter<<<(EE + 255) / 256, 256>>>(src, dst);
    k_gemm   <<<NN / 64, 256>>>(x, ghW1);
    k_pass1  <<<NN / 8, 256>>>(ghb1, ghW2);
    k_pass2  <<<MM / 8, 256>>>(tE, cE, pE, ghb2);
    k_mlp    <<<(MM + 255) / 256, 256>>>(mW1, mb1, mW2, mb2, mW3, mb3, out);
}